// round 4
// baseline (speedup 1.0000x reference)
#include <cuda_runtime.h>
#include <cstdint>

#define L_ 512
#define T_ 64
#define H_ 512
#define B_ 64
#define E_ 256
#define W_ 256
#define V_ 10000
#define G_ 2048
#define NB 128

// ---- static scratch ----
__device__ float d_emb_proj[(size_t)V_ * G_];
__device__ float d_enc[(size_t)L_ * H_ * B_];     // [t][h][b]
__device__ float d_blend1[(size_t)L_ * B_ * W_];  // [l][b][w]
__device__ float d_dhT[2][H_ * B_];               // [h][b]
__device__ float d_blend2[B_ * W_];
__device__ float d_scores[B_ * L_];
__device__ unsigned d_count;
__device__ volatile unsigned d_gen;

__device__ __forceinline__ float sigf(float x) { return 1.0f / (1.0f + __expf(-x)); }
__device__ __forceinline__ float tanh_acc(float x) {
    float e = __expf(2.0f * x);
    return 1.0f - 2.0f / (e + 1.0f);
}
__device__ __forceinline__ float tanh_fast(float x) {
    float r; asm("tanh.approx.f32 %0, %1;" : "=f"(r) : "f"(x)); return r;
}

__device__ __forceinline__ void grid_barrier() {
    __syncthreads();
    if (threadIdx.x == 0) {
        unsigned g = d_gen;
        __threadfence();
        if (atomicAdd(&d_count, 1u) == NB - 1) {
            d_count = 0;
            __threadfence();
            d_gen = g + 1;
        } else {
            while (d_gen == g) { __nanosleep(64); }
            __threadfence();
        }
    }
    __syncthreads();
}

// ============ K1: emb_proj = emb @ Wih^T + bih + bhh ============
__global__ void __launch_bounds__(256) k_embproj(
    const float* __restrict__ emb, const float* __restrict__ Wih,
    const float* __restrict__ bih, const float* __restrict__ bhh)
{
    __shared__ __align__(16) float Ash[32 * 68];
    __shared__ __align__(16) float Bsh[32 * 68];
    const int tid = threadIdx.x;
    const int j0 = blockIdx.x * 64, v0 = blockIdx.y * 64;
    const int li = tid >> 2, kk0 = (tid & 3) * 8;
    const int vi0 = (tid & 15) * 4, ji0 = (tid >> 4) * 4;

    float acc[4][4];
#pragma unroll
    for (int i = 0; i < 4; i++)
#pragma unroll
        for (int jj = 0; jj < 4; jj++) acc[i][jj] = 0.0f;

    for (int kt = 0; kt < 8; kt++) {
        const int k0 = kt * 32;
        float4 x0, x1;
        const int v = v0 + li;
        if (v < V_) {
            const float4* ap = (const float4*)(emb + (size_t)v * E_ + k0 + kk0);
            x0 = __ldg(ap); x1 = __ldg(ap + 1);
        } else { x0 = make_float4(0.f,0.f,0.f,0.f); x1 = x0; }
        Ash[(kk0+0)*68+li]=x0.x; Ash[(kk0+1)*68+li]=x0.y; Ash[(kk0+2)*68+li]=x0.z; Ash[(kk0+3)*68+li]=x0.w;
        Ash[(kk0+4)*68+li]=x1.x; Ash[(kk0+5)*68+li]=x1.y; Ash[(kk0+6)*68+li]=x1.z; Ash[(kk0+7)*68+li]=x1.w;
        const float4* bp = (const float4*)(Wih + (size_t)(j0+li) * E_ + k0 + kk0);
        float4 y0 = __ldg(bp), y1 = __ldg(bp + 1);
        Bsh[(kk0+0)*68+li]=y0.x; Bsh[(kk0+1)*68+li]=y0.y; Bsh[(kk0+2)*68+li]=y0.z; Bsh[(kk0+3)*68+li]=y0.w;
        Bsh[(kk0+4)*68+li]=y1.x; Bsh[(kk0+5)*68+li]=y1.y; Bsh[(kk0+6)*68+li]=y1.z; Bsh[(kk0+7)*68+li]=y1.w;
        __syncthreads();
#pragma unroll
        for (int kk = 0; kk < 32; kk++) {
            float4 av = *(const float4*)&Ash[kk*68 + vi0];
            float4 bv = *(const float4*)&Bsh[kk*68 + ji0];
            acc[0][0]=fmaf(av.x,bv.x,acc[0][0]); acc[0][1]=fmaf(av.x,bv.y,acc[0][1]);
            acc[0][2]=fmaf(av.x,bv.z,acc[0][2]); acc[0][3]=fmaf(av.x,bv.w,acc[0][3]);
            acc[1][0]=fmaf(av.y,bv.x,acc[1][0]); acc[1][1]=fmaf(av.y,bv.y,acc[1][1]);
            acc[1][2]=fmaf(av.y,bv.z,acc[1][2]); acc[1][3]=fmaf(av.y,bv.w,acc[1][3]);
            acc[2][0]=fmaf(av.z,bv.x,acc[2][0]); acc[2][1]=fmaf(av.z,bv.y,acc[2][1]);
            acc[2][2]=fmaf(av.z,bv.z,acc[2][2]); acc[2][3]=fmaf(av.z,bv.w,acc[2][3]);
            acc[3][0]=fmaf(av.w,bv.x,acc[3][0]); acc[3][1]=fmaf(av.w,bv.y,acc[3][1]);
            acc[3][2]=fmaf(av.w,bv.z,acc[3][2]); acc[3][3]=fmaf(av.w,bv.w,acc[3][3]);
        }
        __syncthreads();
    }
    float bj[4];
#pragma unroll
    for (int jj = 0; jj < 4; jj++)
        bj[jj] = __ldg(bih + j0 + ji0 + jj) + __ldg(bhh + j0 + ji0 + jj);
#pragma unroll
    for (int ii = 0; ii < 4; ii++) {
        const int v = v0 + vi0 + ii;
        if (v < V_) {
            float4 o = make_float4(acc[ii][0]+bj[0], acc[ii][1]+bj[1],
                                   acc[ii][2]+bj[2], acc[ii][3]+bj[3]);
            *(float4*)&d_emb_proj[(size_t)v * G_ + j0 + ji0] = o;
        }
    }
}

// ============ K2: persistent encoder ============
__global__ void __launch_bounds__(256) k_encoder(
    const int* __restrict__ ids, const float* __restrict__ Whh)
{
    __shared__ __align__(16) float WshT[512 * 16];
    __shared__ float gsh[16 * 65];
    __shared__ int idsh[64];
    const int tid = threadIdx.x, blk = blockIdx.x;
    const int r = tid & 15, bg = tid >> 4, b0 = bg * 4;
    const int j = (r >> 2) * 512 + blk * 4 + (r & 3);

    for (int idx = tid; idx < 512 * 16; idx += 256) {
        const int k = idx >> 4, r2 = idx & 15;
        const int jj = (r2 >> 2) * 512 + blk * 4 + (r2 & 3);
        WshT[idx] = __ldg(Whh + (size_t)jj * H_ + k);
    }
    const int ho = tid >> 6, bb = tid & 63;
    float c = 0.0f;
    __syncthreads();

    for (int t = 0; t < L_; t++) {
        if (tid < 64) idsh[tid] = __ldg(ids + tid * L_ + t);
        __syncthreads();
        float a0 = d_emb_proj[(size_t)idsh[b0+0] * G_ + j];
        float a1 = d_emb_proj[(size_t)idsh[b0+1] * G_ + j];
        float a2 = d_emb_proj[(size_t)idsh[b0+2] * G_ + j];
        float a3 = d_emb_proj[(size_t)idsh[b0+3] * G_ + j];
        if (t > 0) {
            const float4* hp = (const float4*)(d_enc + (size_t)(t-1) * H_ * B_) + bg;
            const float* wp = WshT + r;
#pragma unroll 8
            for (int k = 0; k < H_; k++) {
                float4 hv = __ldcg(hp + k * 16);
                float  wv = wp[k * 16];
                a0 = fmaf(wv, hv.x, a0); a1 = fmaf(wv, hv.y, a1);
                a2 = fmaf(wv, hv.z, a2); a3 = fmaf(wv, hv.w, a3);
            }
        }
        gsh[r*65 + b0+0] = a0; gsh[r*65 + b0+1] = a1;
        gsh[r*65 + b0+2] = a2; gsh[r*65 + b0+3] = a3;
        __syncthreads();
        {
            float gi = gsh[(0*4+ho)*65 + bb];
            float gf = gsh[(1*4+ho)*65 + bb];
            float gg = gsh[(2*4+ho)*65 + bb];
            float go = gsh[(3*4+ho)*65 + bb];
            c = sigf(gf) * c + sigf(gi) * tanh_acc(gg);
            float h = sigf(go) * tanh_acc(c);
            d_enc[(size_t)t * H_ * B_ + (blk*4+ho)*64 + bb] = h;
        }
        grid_barrier();
    }
}

// ============ K3: blend1[l][b][w] = enc[l] @ W1^T + b1 ============
__global__ void __launch_bounds__(256) k_blend1(
    const float* __restrict__ W1w, const float* __restrict__ W1b)
{
    __shared__ __align__(16) float ensh[32 * 64];
    __shared__ float w1sh[32 * 257];
    const int tid = threadIdx.x, l = blockIdx.x;
    float4 acc[16];
#pragma unroll
    for (int g = 0; g < 16; g++) acc[g] = make_float4(0.f,0.f,0.f,0.f);

    for (int ht = 0; ht < 16; ht++) {
        const float4* ep = (const float4*)(d_enc + (size_t)l * H_ * B_ + (size_t)ht * 32 * 64);
        ((float4*)ensh)[tid]       = ep[tid];
        ((float4*)ensh)[tid + 256] = ep[tid + 256];
#pragma unroll
        for (int rep = 0; rep < 32; rep++) {
            const int lin = rep * 256 + tid;
            const int w = lin >> 5, hh = lin & 31;
            w1sh[hh * 257 + w] = __ldg(W1w + (size_t)w * H_ + ht * 32 + hh);
        }
        __syncthreads();
#pragma unroll
        for (int hh = 0; hh < 32; hh++) {
            const float wv = w1sh[hh * 257 + tid];
            const float4* e4 = (const float4*)(ensh + hh * 64);
#pragma unroll
            for (int g = 0; g < 16; g++) {
                float4 ev = e4[g];
                acc[g].x = fmaf(wv, ev.x, acc[g].x);
                acc[g].y = fmaf(wv, ev.y, acc[g].y);
                acc[g].z = fmaf(wv, ev.z, acc[g].z);
                acc[g].w = fmaf(wv, ev.w, acc[g].w);
            }
        }
        __syncthreads();
    }
    const float bias = __ldg(W1b + tid);
    float* outp = d_blend1 + (size_t)l * B_ * W_ + tid;
#pragma unroll
    for (int g = 0; g < 16; g++) {
        outp[(g*4+0) * W_] = acc[g].x + bias;
        outp[(g*4+1) * W_] = acc[g].y + bias;
        outp[(g*4+2) * W_] = acc[g].z + bias;
        outp[(g*4+3) * W_] = acc[g].w + bias;
    }
}

// ============ K4: persistent decoder ============
__global__ void __launch_bounds__(256) k_decoder(
    const float* __restrict__ Whh, const float* __restrict__ bih,
    const float* __restrict__ bhh, const float* __restrict__ W2w,
    const float* __restrict__ W2b, const float* __restrict__ vtw,
    const float* __restrict__ h0, float* __restrict__ out)
{
    __shared__ __align__(16) float WshT[512 * 16];
    __shared__ float gsh[16 * 65];
    const int tid = threadIdx.x, blk = blockIdx.x;
    const int r = tid & 15, bg = tid >> 4, b0 = bg * 4;
    const int j = (r >> 2) * 512 + blk * 4 + (r & 3);
    const float gb = __ldg(bih + j) + __ldg(bhh + j);     // x_dec == 0

    for (int idx = tid; idx < 512 * 16; idx += 256) {
        const int k = idx >> 4, r2 = idx & 15;
        const int jj = (r2 >> 2) * 512 + blk * 4 + (r2 & 3);
        WshT[idx] = __ldg(Whh + (size_t)jj * H_ + k);
    }
    {   // transpose h0 [b][h] -> d_dhT[0] [h][b]
        const int gt = blk * 256 + tid;
        const int hh = gt >> 6, b = gt & 63;
        d_dhT[0][hh * 64 + b] = __ldg(h0 + (size_t)b * H_ + hh);
    }
    const int ho = tid >> 6, bb = tid & 63;
    float c = __ldg(d_enc + (size_t)(L_-1) * H_ * B_ + (blk*4+ho)*64 + bb);  // c0

    const int lane = tid & 31, wrp = tid >> 5;
    const int gw = blk * 8 + wrp;
    const int cb = gw & 63, lbase = (gw >> 6) * 32;
    const float4 vta = __ldg((const float4*)vtw + lane);
    const float4 vtb = __ldg((const float4*)vtw + 32 + lane);

    grid_barrier();

    for (int s = 0; s < T_; s++) {
        const int cur = s & 1, nxt = cur ^ 1;

        // ---- A: gates + cell update ----
        float a0 = gb, a1 = gb, a2 = gb, a3 = gb;
        {
            const float4* hp = (const float4*)d_dhT[cur] + bg;
            const float* wp = WshT + r;
#pragma unroll 8
            for (int k = 0; k < H_; k++) {
                float4 hv = __ldcg(hp + k * 16);
                float  wv = wp[k * 16];
                a0 = fmaf(wv, hv.x, a0); a1 = fmaf(wv, hv.y, a1);
                a2 = fmaf(wv, hv.z, a2); a3 = fmaf(wv, hv.w, a3);
            }
        }
        gsh[r*65 + b0+0] = a0; gsh[r*65 + b0+1] = a1;
        gsh[r*65 + b0+2] = a2; gsh[r*65 + b0+3] = a3;
        __syncthreads();
        {
            float gi = gsh[(0*4+ho)*65 + bb];
            float gf = gsh[(1*4+ho)*65 + bb];
            float gg = gsh[(2*4+ho)*65 + bb];
            float go = gsh[(3*4+ho)*65 + bb];
            c = sigf(gf) * c + sigf(gi) * tanh_acc(gg);
            float h = sigf(go) * tanh_acc(c);
            d_dhT[nxt][(blk*4+ho)*64 + bb] = h;
        }
        grid_barrier();

        // ---- B: blend2[b][w] = h @ W2^T + b2 ----
        if (blk < 64) {
            const int b = blk;
            const float* hT = d_dhT[nxt];
            float acc = __ldg(W2b + tid);
            const float4* w2 = (const float4*)(W2w + (size_t)tid * 512);
#pragma unroll 8
            for (int h4 = 0; h4 < 128; h4++) {
                float4 w = __ldg(w2 + h4);
                acc = fmaf(__ldcg(hT + (h4*4+0)*64 + b), w.x, acc);
                acc = fmaf(__ldcg(hT + (h4*4+1)*64 + b), w.y, acc);
                acc = fmaf(__ldcg(hT + (h4*4+2)*64 + b), w.z, acc);
                acc = fmaf(__ldcg(hT + (h4*4+3)*64 + b), w.w, acc);
            }
            d_blend2[b * 256 + tid] = acc;
        }
        grid_barrier();

        // ---- C: scores[b][l] = tanh(blend1+blend2) . vt ----
        {
            float4 b2a = __ldcg((const float4*)(d_blend2 + cb * 256) + lane);
            float4 b2b = __ldcg((const float4*)(d_blend2 + cb * 256) + 32 + lane);
            for (int li = 0; li < 32; li++) {
                const int l = lbase + li;
                const float4* bp = (const float4*)(d_blend1 + ((size_t)l * 64 + cb) * 256);
                float4 x = __ldg(bp + lane), y = __ldg(bp + 32 + lane);
                float sv = tanh_fast(x.x + b2a.x) * vta.x + tanh_fast(x.y + b2a.y) * vta.y
                         + tanh_fast(x.z + b2a.z) * vta.z + tanh_fast(x.w + b2a.w) * vta.w
                         + tanh_fast(y.x + b2b.x) * vtb.x + tanh_fast(y.y + b2b.y) * vtb.y
                         + tanh_fast(y.z + b2b.z) * vtb.z + tanh_fast(y.w + b2b.w) * vtb.w;
#pragma unroll
                for (int o = 16; o > 0; o >>= 1) sv += __shfl_xor_sync(0xFFFFFFFFu, sv, o);
                if (lane == 0) d_scores[cb * 512 + l] = sv;
            }
        }
        grid_barrier();

        // ---- D: log-softmax over l, write out[l][b][s] ----
        if (blk < 64) {
            const int b = blk;
            float s0 = __ldcg(d_scores + b * 512 + tid);
            float s1 = __ldcg(d_scores + b * 512 + tid + 256);
            float m = fmaxf(s0, s1);
            gsh[tid] = m; __syncthreads();
            for (int o = 128; o > 0; o >>= 1) {
                if (tid < o) gsh[tid] = fmaxf(gsh[tid], gsh[tid + o]);
                __syncthreads();
            }
            m = gsh[0]; __syncthreads();
            float se = __expf(s0 - m) + __expf(s1 - m);
            gsh[tid] = se; __syncthreads();
            for (int o = 128; o > 0; o >>= 1) {
                if (tid < o) gsh[tid] += gsh[tid + o];
                __syncthreads();
            }
            const float lse = m + __logf(gsh[0]);
            out[((size_t)tid       * 64 + b) * 64 + s] = s0 - lse;
            out[((size_t)(tid+256) * 64 + b) * 64 + s] = s1 - lse;
        }
        __syncthreads();   // protect gsh before next iteration's A
    }
}

extern "C" void kernel_launch(void* const* d_in, const int* in_sizes, int n_in,
                              void* d_out, int out_size) {
    const int*   ids     = (const int*)  d_in[0];
    const float* emb     = (const float*)d_in[1];
    const float* eWih    = (const float*)d_in[2];
    const float* eWhh    = (const float*)d_in[3];
    const float* ebih    = (const float*)d_in[4];
    const float* ebhh    = (const float*)d_in[5];
    const float* dWhh    = (const float*)d_in[7];
    const float* dbih    = (const float*)d_in[8];
    const float* dbhh    = (const float*)d_in[9];
    const float* W1w     = (const float*)d_in[10];
    const float* W1b     = (const float*)d_in[11];
    const float* W2w     = (const float*)d_in[12];
    const float* W2b     = (const float*)d_in[13];
    const float* vtw     = (const float*)d_in[14];
    const float* h0      = (const float*)d_in[16];
    float* out = (float*)d_out;

    dim3 g1(G_ / 64, (V_ + 63) / 64);
    k_embproj<<<g1, 256>>>(emb, eWih, ebih, ebhh);
    k_encoder<<<NB, 256>>>(ids, eWhh);
    k_blend1<<<L_, 256>>>(W1w, W1b);
    k_decoder<<<NB, 256>>>(dWhh, dbih, dbhh, W2w, W2b, vtw, h0, out);
}

// round 5
// speedup vs baseline: 5.4158x; 5.4158x over previous
#include <cuda_runtime.h>
#include <cstdint>

#define L_ 512
#define T_ 64
#define H_ 512
#define B_ 64
#define E_ 256
#define W_ 256
#define V_ 10000
#define G_ 2048
#define NB 128

// ---- static scratch ----
__device__ float d_emb_proj[(size_t)V_ * G_];
__device__ float d_enc[(size_t)L_ * H_ * B_];     // [t][h][b]
__device__ float d_blend1[(size_t)L_ * B_ * W_];  // [l][b][w]
__device__ float d_dhT[2][H_ * B_];               // [h][b]
__device__ float d_blend2[B_ * W_];
__device__ float d_scores[B_ * L_];
__device__ unsigned d_count;                       // monotonic arrivals
__device__ unsigned d_gen;                         // monotonic completed barriers

__device__ __forceinline__ float sigf(float x) { return 1.0f / (1.0f + __expf(-x)); }
__device__ __forceinline__ float tanh_acc(float x) {
    float e = __expf(2.0f * x);
    return 1.0f - 2.0f / (e + 1.0f);
}
__device__ __forceinline__ float tanh_fast(float x) {
    float r; asm("tanh.approx.f32 %0, %1;" : "=f"(r) : "f"(x)); return r;
}

__device__ __forceinline__ unsigned ld_gen_acq() {
    unsigned v;
    asm volatile("ld.acquire.gpu.global.u32 %0, [%1];" : "=r"(v) : "l"(&d_gen) : "memory");
    return v;
}

// Monotonic sense-free grid barrier. target = absolute completed-barrier count.
__device__ __forceinline__ void grid_barrier(unsigned target) {
    __syncthreads();
    if (threadIdx.x == 0) {
        unsigned prev;
        asm volatile("atom.add.release.gpu.global.u32 %0, [%1], 1;"
                     : "=r"(prev) : "l"(&d_count) : "memory");
        if (prev + 1 == target * NB) {
            asm volatile("st.release.gpu.global.u32 [%0], %1;"
                         :: "l"(&d_gen), "r"(target) : "memory");
        } else {
            while (ld_gen_acq() < target) { __nanosleep(32); }
        }
    }
    __syncthreads();
}

// Stage 128KB [512][64] h-slice into SMEM via cp.async (all 256 threads).
__device__ __forceinline__ void stage_h(const float* __restrict__ src, float* hsh, int tid) {
    uint32_t hb = (uint32_t)__cvta_generic_to_shared(hsh);
    const float4* s4 = (const float4*)src;
#pragma unroll
    for (int i = 0; i < 32; i++) {
        int idx = i * 256 + tid;
        asm volatile("cp.async.cg.shared.global [%0], [%1], 16;"
                     :: "r"(hb + idx * 16), "l"(s4 + idx));
    }
    asm volatile("cp.async.commit_group;");
    asm volatile("cp.async.wait_group 0;" ::: "memory");
}

// ============ K1: emb_proj = emb @ Wih^T + bih + bhh ============
__global__ void __launch_bounds__(256) k_embproj(
    const float* __restrict__ emb, const float* __restrict__ Wih,
    const float* __restrict__ bih, const float* __restrict__ bhh)
{
    __shared__ __align__(16) float Ash[32 * 68];
    __shared__ __align__(16) float Bsh[32 * 68];
    const int tid = threadIdx.x;
    const int j0 = blockIdx.x * 64, v0 = blockIdx.y * 64;
    const int li = tid >> 2, kk0 = (tid & 3) * 8;
    const int vi0 = (tid & 15) * 4, ji0 = (tid >> 4) * 4;

    float acc[4][4];
#pragma unroll
    for (int i = 0; i < 4; i++)
#pragma unroll
        for (int jj = 0; jj < 4; jj++) acc[i][jj] = 0.0f;

    for (int kt = 0; kt < 8; kt++) {
        const int k0 = kt * 32;
        float4 x0, x1;
        const int v = v0 + li;
        if (v < V_) {
            const float4* ap = (const float4*)(emb + (size_t)v * E_ + k0 + kk0);
            x0 = __ldg(ap); x1 = __ldg(ap + 1);
        } else { x0 = make_float4(0.f,0.f,0.f,0.f); x1 = x0; }
        Ash[(kk0+0)*68+li]=x0.x; Ash[(kk0+1)*68+li]=x0.y; Ash[(kk0+2)*68+li]=x0.z; Ash[(kk0+3)*68+li]=x0.w;
        Ash[(kk0+4)*68+li]=x1.x; Ash[(kk0+5)*68+li]=x1.y; Ash[(kk0+6)*68+li]=x1.z; Ash[(kk0+7)*68+li]=x1.w;
        const float4* bp = (const float4*)(Wih + (size_t)(j0+li) * E_ + k0 + kk0);
        float4 y0 = __ldg(bp), y1 = __ldg(bp + 1);
        Bsh[(kk0+0)*68+li]=y0.x; Bsh[(kk0+1)*68+li]=y0.y; Bsh[(kk0+2)*68+li]=y0.z; Bsh[(kk0+3)*68+li]=y0.w;
        Bsh[(kk0+4)*68+li]=y1.x; Bsh[(kk0+5)*68+li]=y1.y; Bsh[(kk0+6)*68+li]=y1.z; Bsh[(kk0+7)*68+li]=y1.w;
        __syncthreads();
#pragma unroll
        for (int kk = 0; kk < 32; kk++) {
            float4 av = *(const float4*)&Ash[kk*68 + vi0];
            float4 bv = *(const float4*)&Bsh[kk*68 + ji0];
            acc[0][0]=fmaf(av.x,bv.x,acc[0][0]); acc[0][1]=fmaf(av.x,bv.y,acc[0][1]);
            acc[0][2]=fmaf(av.x,bv.z,acc[0][2]); acc[0][3]=fmaf(av.x,bv.w,acc[0][3]);
            acc[1][0]=fmaf(av.y,bv.x,acc[1][0]); acc[1][1]=fmaf(av.y,bv.y,acc[1][1]);
            acc[1][2]=fmaf(av.y,bv.z,acc[1][2]); acc[1][3]=fmaf(av.y,bv.w,acc[1][3]);
            acc[2][0]=fmaf(av.z,bv.x,acc[2][0]); acc[2][1]=fmaf(av.z,bv.y,acc[2][1]);
            acc[2][2]=fmaf(av.z,bv.z,acc[2][2]); acc[2][3]=fmaf(av.z,bv.w,acc[2][3]);
            acc[3][0]=fmaf(av.w,bv.x,acc[3][0]); acc[3][1]=fmaf(av.w,bv.y,acc[3][1]);
            acc[3][2]=fmaf(av.w,bv.z,acc[3][2]); acc[3][3]=fmaf(av.w,bv.w,acc[3][3]);
        }
        __syncthreads();
    }
    float bj[4];
#pragma unroll
    for (int jj = 0; jj < 4; jj++)
        bj[jj] = __ldg(bih + j0 + ji0 + jj) + __ldg(bhh + j0 + ji0 + jj);
#pragma unroll
    for (int ii = 0; ii < 4; ii++) {
        const int v = v0 + vi0 + ii;
        if (v < V_) {
            float4 o = make_float4(acc[ii][0]+bj[0], acc[ii][1]+bj[1],
                                   acc[ii][2]+bj[2], acc[ii][3]+bj[3]);
            *(float4*)&d_emb_proj[(size_t)v * G_ + j0 + ji0] = o;
        }
    }
}

// ============ K2: persistent encoder (SMEM-staged h) ============
// smem: WshT[512*16] | hsh[512*64] | gsh[16*65] | idsA[64] idsB[64]
__global__ void __launch_bounds__(256) k_encoder(
    const int* __restrict__ ids, const float* __restrict__ Whh)
{
    extern __shared__ __align__(16) float sm[];
    float* WshT = sm;                  // 8192 floats
    float* hsh  = sm + 8192;           // 32768 floats
    float* gsh  = sm + 8192 + 32768;   // 1040 floats
    int*   idsA = (int*)(gsh + 1040);
    int*   idsB = idsA + 64;

    const int tid = threadIdx.x, blk = blockIdx.x;
    const int r = tid & 15, bg = tid >> 4, b0 = bg * 4;
    const int j = (r >> 2) * 512 + blk * 4 + (r & 3);
    unsigned g0 = 0;
    if (tid == 0) g0 = ld_gen_acq();

    for (int idx = tid; idx < 8192; idx += 256) {
        const int k = idx >> 4, r2 = idx & 15;
        const int jj = (r2 >> 2) * 512 + blk * 4 + (r2 & 3);
        WshT[idx] = __ldg(Whh + (size_t)jj * H_ + k);
    }
    if (tid < 64) idsA[tid] = __ldg(ids + tid * L_);
    const int ho = tid >> 6, bb = tid & 63;
    float c = 0.0f;
    __syncthreads();

    for (int t = 0; t < L_; t++) {
        int* cur_ids = (t & 1) ? idsB : idsA;
        int* nxt_ids = (t & 1) ? idsA : idsB;
        float a0 = __ldg(&d_emb_proj[(size_t)cur_ids[b0+0] * G_ + j]);
        float a1 = __ldg(&d_emb_proj[(size_t)cur_ids[b0+1] * G_ + j]);
        float a2 = __ldg(&d_emb_proj[(size_t)cur_ids[b0+2] * G_ + j]);
        float a3 = __ldg(&d_emb_proj[(size_t)cur_ids[b0+3] * G_ + j]);
        if (tid < 64 && t + 1 < L_) nxt_ids[tid] = __ldg(ids + tid * L_ + t + 1);

        if (t > 0) {
            stage_h(d_enc + (size_t)(t - 1) * H_ * B_, hsh, tid);
            __syncthreads();
            const float* hp = hsh + b0;
            const float* wp = WshT + r;
#pragma unroll 8
            for (int k = 0; k < 512; k++) {
                float4 hv = *(const float4*)(hp + (k << 6));
                float  wv = wp[k << 4];
                a0 = fmaf(wv, hv.x, a0); a1 = fmaf(wv, hv.y, a1);
                a2 = fmaf(wv, hv.z, a2); a3 = fmaf(wv, hv.w, a3);
            }
        }
        gsh[r*65 + b0+0] = a0; gsh[r*65 + b0+1] = a1;
        gsh[r*65 + b0+2] = a2; gsh[r*65 + b0+3] = a3;
        __syncthreads();
        {
            float gi = gsh[(0*4+ho)*65 + bb];
            float gf = gsh[(1*4+ho)*65 + bb];
            float gg = gsh[(2*4+ho)*65 + bb];
            float go = gsh[(3*4+ho)*65 + bb];
            c = sigf(gf) * c + sigf(gi) * tanh_acc(gg);
            float h = sigf(go) * tanh_acc(c);
            d_enc[(size_t)t * H_ * B_ + (blk*4+ho)*64 + bb] = h;
        }
        if (t + 1 < L_) grid_barrier(g0 + t + 1);
    }
}

// ============ K3: blend1[l][b][w] = enc[l] @ W1^T + b1 ============
__global__ void __launch_bounds__(256) k_blend1(
    const float* __restrict__ W1w, const float* __restrict__ W1b)
{
    __shared__ __align__(16) float ensh[32 * 64];
    __shared__ float w1sh[32 * 257];
    const int tid = threadIdx.x, l = blockIdx.x;
    float4 acc[16];
#pragma unroll
    for (int g = 0; g < 16; g++) acc[g] = make_float4(0.f,0.f,0.f,0.f);

    for (int ht = 0; ht < 16; ht++) {
        const float4* ep = (const float4*)(d_enc + (size_t)l * H_ * B_ + (size_t)ht * 32 * 64);
        ((float4*)ensh)[tid]       = __ldg(ep + tid);
        ((float4*)ensh)[tid + 256] = __ldg(ep + tid + 256);
#pragma unroll
        for (int rep = 0; rep < 32; rep++) {
            const int lin = rep * 256 + tid;
            const int w = lin >> 5, hh = lin & 31;
            w1sh[hh * 257 + w] = __ldg(W1w + (size_t)w * H_ + ht * 32 + hh);
        }
        __syncthreads();
#pragma unroll
        for (int hh = 0; hh < 32; hh++) {
            const float wv = w1sh[hh * 257 + tid];
            const float4* e4 = (const float4*)(ensh + hh * 64);
#pragma unroll
            for (int g = 0; g < 16; g++) {
                float4 ev = e4[g];
                acc[g].x = fmaf(wv, ev.x, acc[g].x);
                acc[g].y = fmaf(wv, ev.y, acc[g].y);
                acc[g].z = fmaf(wv, ev.z, acc[g].z);
                acc[g].w = fmaf(wv, ev.w, acc[g].w);
            }
        }
        __syncthreads();
    }
    const float bias = __ldg(W1b + tid);
    float* outp = d_blend1 + (size_t)l * B_ * W_ + tid;
#pragma unroll
    for (int g = 0; g < 16; g++) {
        outp[(g*4+0) * W_] = acc[g].x + bias;
        outp[(g*4+1) * W_] = acc[g].y + bias;
        outp[(g*4+2) * W_] = acc[g].z + bias;
        outp[(g*4+3) * W_] = acc[g].w + bias;
    }
}

// ============ K4: persistent decoder (SMEM-staged h, SMEM W2 rows) ============
// smem: WshT[8192] | hsh[32768] | gsh[1040] | w2sh[1024] | w2bs[2]
__global__ void __launch_bounds__(256) k_decoder(
    const float* __restrict__ Whh, const float* __restrict__ bih,
    const float* __restrict__ bhh, const float* __restrict__ W2w,
    const float* __restrict__ W2b, const float* __restrict__ vtw,
    const float* __restrict__ h0, float* __restrict__ out)
{
    extern __shared__ __align__(16) float sm[];
    float* WshT = sm;                   // 8192
    float* hsh  = sm + 8192;            // 32768
    float* gsh  = sm + 40960;           // 1040
    float* w2sh = sm + 42000;           // 1024
    float* w2bs = sm + 43024;           // 2

    const int tid = threadIdx.x, blk = blockIdx.x;
    const int r = tid & 15, bg = tid >> 4, b0 = bg * 4;
    const int j = (r >> 2) * 512 + blk * 4 + (r & 3);
    const float gb = __ldg(bih + j) + __ldg(bhh + j);    // x_dec == 0
    unsigned g0 = 0;
    if (tid == 0) g0 = ld_gen_acq();

    for (int idx = tid; idx < 8192; idx += 256) {
        const int k = idx >> 4, r2 = idx & 15;
        const int jj = (r2 >> 2) * 512 + blk * 4 + (r2 & 3);
        WshT[idx] = __ldg(Whh + (size_t)jj * H_ + k);
    }
    // W2 rows owned by this block: w = 2*blk, 2*blk+1
    for (int idx = tid; idx < 1024; idx += 256) {
        const int row = idx >> 9, hh = idx & 511;
        w2sh[idx] = __ldg(W2w + (size_t)(2*blk + row) * H_ + hh);
    }
    if (tid < 2) w2bs[tid] = __ldg(W2b + 2*blk + tid);
    {   // transpose h0 [b][h] -> d_dhT[0] [h][b]
        const int gt = blk * 256 + tid;
        const int hh = gt >> 6, b = gt & 63;
        d_dhT[0][hh * 64 + b] = __ldg(h0 + (size_t)b * H_ + hh);
    }
    const int ho = tid >> 6, bb = tid & 63;
    float c = __ldg(d_enc + (size_t)(L_-1) * H_ * B_ + (blk*4+ho)*64 + bb);  // c0

    const int lane = tid & 31, wrp = tid >> 5;
    const int gw = blk * 8 + wrp;
    const int cb = gw & 63, lbase = (gw >> 6) * 32;
    const float4 vta = __ldg((const float4*)vtw + lane);
    const float4 vtb = __ldg((const float4*)vtw + 32 + lane);
    // phase-B mapping: thread = (klo, w_local, b)
    const int pb_klo = tid >> 7, pb_wl = (tid >> 6) & 1, pb_b = tid & 63;

    grid_barrier(g0 + 1);
    const unsigned base = g0 + 1;

    for (int s = 0; s < T_; s++) {
        const int cur = s & 1, nxt = cur ^ 1;

        // ---- A: gates from SMEM-staged h, cell update ----
        stage_h(d_dhT[cur], hsh, tid);
        __syncthreads();
        float a0 = gb, a1 = gb, a2 = gb, a3 = gb;
        {
            const float* hp = hsh + b0;
            const float* wp = WshT + r;
#pragma unroll 8
            for (int k = 0; k < 512; k++) {
                float4 hv = *(const float4*)(hp + (k << 6));
                float  wv = wp[k << 4];
                a0 = fmaf(wv, hv.x, a0); a1 = fmaf(wv, hv.y, a1);
                a2 = fmaf(wv, hv.z, a2); a3 = fmaf(wv, hv.w, a3);
            }
        }
        gsh[r*65 + b0+0] = a0; gsh[r*65 + b0+1] = a1;
        gsh[r*65 + b0+2] = a2; gsh[r*65 + b0+3] = a3;
        __syncthreads();
        {
            float gi = gsh[(0*4+ho)*65 + bb];
            float gf = gsh[(1*4+ho)*65 + bb];
            float gg = gsh[(2*4+ho)*65 + bb];
            float go = gsh[(3*4+ho)*65 + bb];
            c = sigf(gf) * c + sigf(gi) * tanh_acc(gg);
            float h = sigf(go) * tanh_acc(c);
            d_dhT[nxt][(blk*4+ho)*64 + bb] = h;
        }
        grid_barrier(base + 3*s + 1);

        // ---- B: blend2[b][w] for this block's 2 W2 rows, from SMEM h ----
        stage_h(d_dhT[nxt], hsh, tid);
        __syncthreads();
        {
            float part = 0.0f;
            const float* hp = hsh + pb_b + pb_klo * 256 * 64;
            const float* wp = w2sh + pb_wl * 512 + pb_klo * 256;
#pragma unroll 8
            for (int k = 0; k < 256; k++)
                part = fmaf(wp[k], hp[k << 6], part);
            gsh[tid] = part;
        }
        __syncthreads();
        if (tid < 128) {
            float tot = gsh[tid] + gsh[tid + 128] + w2bs[(tid >> 6) & 1];
            const int b = tid & 63, wl = (tid >> 6) & 1;
            d_blend2[b * 256 + 2*blk + wl] = tot;
        }
        grid_barrier(base + 3*s + 2);

        // ---- C: scores[b][l] = tanh(blend1+blend2) . vt ----
        {
            float4 b2a = __ldcg((const float4*)(d_blend2 + cb * 256) + lane);
            float4 b2b = __ldcg((const float4*)(d_blend2 + cb * 256) + 32 + lane);
            for (int li = 0; li < 32; li++) {
                const int l = lbase + li;
                const float4* bp = (const float4*)(d_blend1 + ((size_t)l * 64 + cb) * 256);
                float4 x = __ldg(bp + lane), y = __ldg(bp + 32 + lane);
                float sv = tanh_fast(x.x + b2a.x) * vta.x + tanh_fast(x.y + b2a.y) * vta.y
                         + tanh_fast(x.z + b2a.z) * vta.z + tanh_fast(x.w + b2a.w) * vta.w
                         + tanh_fast(y.x + b2b.x) * vtb.x + tanh_fast(y.y + b2b.y) * vtb.y
                         + tanh_fast(y.z + b2b.z) * vtb.z + tanh_fast(y.w + b2b.w) * vtb.w;
#pragma unroll
                for (int o = 16; o > 0; o >>= 1) sv += __shfl_xor_sync(0xFFFFFFFFu, sv, o);
                if (lane == 0) d_scores[cb * 512 + l] = sv;
            }
        }
        grid_barrier(base + 3*s + 3);

        // ---- D: log-softmax over l, write out[l][b][s] ----
        if (blk < 64) {
            const int b = blk;
            float s0 = __ldcg(d_scores + b * 512 + tid);
            float s1 = __ldcg(d_scores + b * 512 + tid + 256);
            float m = fmaxf(s0, s1);
            gsh[tid] = m; __syncthreads();
            for (int o = 128; o > 0; o >>= 1) {
                if (tid < o) gsh[tid] = fmaxf(gsh[tid], gsh[tid + o]);
                __syncthreads();
            }
            m = gsh[0]; __syncthreads();
            float se = __expf(s0 - m) + __expf(s1 - m);
            gsh[tid] = se; __syncthreads();
            for (int o = 128; o > 0; o >>= 1) {
                if (tid < o) gsh[tid] += gsh[tid + o];
                __syncthreads();
            }
            const float lse = m + __logf(gsh[0]);
            out[((size_t)tid       * 64 + b) * 64 + s] = s0 - lse;
            out[((size_t)(tid+256) * 64 + b) * 64 + s] = s1 - lse;
        }
        __syncthreads();   // protect gsh before next step's phase A
    }
}

extern "C" void kernel_launch(void* const* d_in, const int* in_sizes, int n_in,
                              void* d_out, int out_size) {
    const int*   ids  = (const int*)  d_in[0];
    const float* emb  = (const float*)d_in[1];
    const float* eWih = (const float*)d_in[2];
    const float* eWhh = (const float*)d_in[3];
    const float* ebih = (const float*)d_in[4];
    const float* ebhh = (const float*)d_in[5];
    const float* dWhh = (const float*)d_in[7];
    const float* dbih = (const float*)d_in[8];
    const float* dbhh = (const float*)d_in[9];
    const float* W1w  = (const float*)d_in[10];
    const float* W1b  = (const float*)d_in[11];
    const float* W2w  = (const float*)d_in[12];
    const float* W2b  = (const float*)d_in[13];
    const float* vtw  = (const float*)d_in[14];
    const float* h0   = (const float*)d_in[16];
    float* out = (float*)d_out;

    static int smem_set = 0;
    const int enc_smem = (8192 + 32768 + 1040) * 4 + 128 * 4;       // 168512
    const int dec_smem = (8192 + 32768 + 1040 + 1024 + 2) * 4;      // 172104
    if (!smem_set) {
        cudaFuncSetAttribute(k_encoder, cudaFuncAttributeMaxDynamicSharedMemorySize, enc_smem);
        cudaFuncSetAttribute(k_decoder, cudaFuncAttributeMaxDynamicSharedMemorySize, dec_smem);
        smem_set = 1;
    }

    dim3 g1(G_ / 64, (V_ + 63) / 64);
    k_embproj<<<g1, 256>>>(emb, eWih, ebih, ebhh);
    k_encoder<<<NB, 256, enc_smem>>>(ids, eWhh);
    k_blend1<<<L_, 256>>>(W1w, W1b);
    k_decoder<<<NB, 256, dec_smem>>>(dWhh, dbih, dbhh, W2w, W2b, vtw, h0, out);
}